// round 1
// baseline (speedup 1.0000x reference)
#include <cuda_runtime.h>
#include <cstdint>

#define N_ROWS   262144
#define IN_D     256
#define OUT_D    256

#define TILE_M   256      // rows per CTA
#define SUB_M    128      // rows per inner subtile
#define PAD      16       // bytes of padding per smem row (bank-conflict-free)
#define LDA      (IN_D + PAD)   // 272 bytes per s8 row

#define SMEM_B_BYTES   (OUT_D * LDA)           // 69632
#define SMEM_A_BYTES   (SUB_M * LDA)           // 34816
#define SMEM_SC_BYTES  (OUT_D * 4)             // 1024
#define SMEM_BYTES     (SMEM_B_BYTES + SMEM_A_BYTES + SMEM_SC_BYTES)  // 105472

// Prepacked sign(weight) as s8, [OUT_D][IN_D]
__device__ __align__(16) int8_t g_wb[OUT_D * IN_D];

__device__ __forceinline__ int sgn(float f) {
    return (f > 0.0f) - (f < 0.0f);   // matches jnp.sign incl. sign(0)=0
}

__global__ void prepack_w_kernel(const float* __restrict__ w) {
    int idx = blockIdx.x * 256 + threadIdx.x;   // 65536 total
    g_wb[idx] = (int8_t)sgn(w[idx]);
}

__global__ void __launch_bounds__(512, 1)
xnor_gemm_kernel(const float* __restrict__ x,
                 const float* __restrict__ scale,
                 float* __restrict__ out) {
    extern __shared__ int8_t smem[];
    int8_t* sB     = smem;                                   // [OUT_D][LDA]
    int8_t* sA     = smem + SMEM_B_BYTES;                    // [SUB_M][LDA]
    float*  sScale = (float*)(smem + SMEM_B_BYTES + SMEM_A_BYTES);

    const int tid  = threadIdx.x;
    const int lane = tid & 31;
    const int warp = tid >> 5;
    const int tig  = lane & 3;     // thread-in-group
    const int grp  = lane >> 2;    // group id (0..7)
    const int mw   = warp & 3;     // warp M index (0..3) -> 32 rows each
    const int nw   = warp >> 2;    // warp N index (0..3) -> 64 cols each

    // ---- stage prepacked weights (64KB s8) into padded smem ----
    {
        const int4* gw4 = (const int4*)g_wb;   // 4096 int4
        #pragma unroll
        for (int i = 0; i < 8; i++) {
            int fid  = tid + i * 512;          // 0..4095
            int row  = fid >> 4;               // 16 int4 per 256B row
            int c16  = fid & 15;
            int4 v   = gw4[fid];
            *(int4*)(sB + row * LDA + c16 * 16) = v;
        }
        if (tid < OUT_D) sScale[tid] = scale[tid];
    }

    const int rowBase = blockIdx.x * TILE_M;

    for (int sub = 0; sub < 2; sub++) {
        // ---- load x subtile [128][256] fp32, sign-convert, store s8 smem ----
        const float4* gx4 = (const float4*)(x + (size_t)(rowBase + sub * SUB_M) * IN_D);
        #pragma unroll
        for (int i = 0; i < 16; i++) {
            int fid = tid + i * 512;           // 0..8191 float4s
            int r   = fid >> 6;                // 64 float4 per row
            int c4  = fid & 63;
            float4 v = gx4[fid];
            unsigned int p = ((unsigned int)(unsigned char)(int8_t)sgn(v.x))
                           | ((unsigned int)(unsigned char)(int8_t)sgn(v.y) << 8)
                           | ((unsigned int)(unsigned char)(int8_t)sgn(v.z) << 16)
                           | ((unsigned int)(unsigned char)(int8_t)sgn(v.w) << 24);
            *(unsigned int*)(sA + r * LDA + c4 * 4) = p;
        }
        __syncthreads();

        // ---- MMA mainloop: warp tile 32x64, m16n8k32 s8 ----
        int acc[2][8][4];
        #pragma unroll
        for (int mi = 0; mi < 2; mi++)
            #pragma unroll
            for (int nf = 0; nf < 8; nf++)
                #pragma unroll
                for (int c = 0; c < 4; c++)
                    acc[mi][nf][c] = 0;

        const int aRowBase = mw * 32;
        const int nColBase = nw * 64;

        #pragma unroll
        for (int ks = 0; ks < 8; ks++) {
            const int kOff = ks * 32;
            unsigned int a[2][4];
            #pragma unroll
            for (int mi = 0; mi < 2; mi++) {
                const int8_t* ap = sA + (aRowBase + mi * 16 + grp) * LDA + kOff + tig * 4;
                a[mi][0] = *(const unsigned int*)(ap);
                a[mi][1] = *(const unsigned int*)(ap + 8 * LDA);
                a[mi][2] = *(const unsigned int*)(ap + 16);
                a[mi][3] = *(const unsigned int*)(ap + 8 * LDA + 16);
            }
            #pragma unroll
            for (int nf = 0; nf < 8; nf++) {
                const int8_t* bp = sB + (nColBase + nf * 8 + grp) * LDA + kOff + tig * 4;
                unsigned int b0 = *(const unsigned int*)(bp);
                unsigned int b1 = *(const unsigned int*)(bp + 16);
                #pragma unroll
                for (int mi = 0; mi < 2; mi++) {
                    asm volatile(
                        "mma.sync.aligned.m16n8k32.row.col.s32.s8.s8.s32 "
                        "{%0,%1,%2,%3}, {%4,%5,%6,%7}, {%8,%9}, {%0,%1,%2,%3};"
                        : "+r"(acc[mi][nf][0]), "+r"(acc[mi][nf][1]),
                          "+r"(acc[mi][nf][2]), "+r"(acc[mi][nf][3])
                        : "r"(a[mi][0]), "r"(a[mi][1]), "r"(a[mi][2]), "r"(a[mi][3]),
                          "r"(b0), "r"(b1));
                }
            }
        }
        __syncthreads();   // all warps done reading sA before next subtile overwrite

        // ---- epilogue: y = float(acc) * scale[col], 8B vector stores ----
        const size_t outRow0 = (size_t)rowBase + sub * SUB_M + mw * 32;
        #pragma unroll
        for (int mi = 0; mi < 2; mi++) {
            size_t r0 = outRow0 + mi * 16 + grp;
            #pragma unroll
            for (int nf = 0; nf < 8; nf++) {
                int col = nColBase + nf * 8 + tig * 2;
                float s0 = sScale[col];
                float s1 = sScale[col + 1];
                float2 v0 = make_float2((float)acc[mi][nf][0] * s0,
                                        (float)acc[mi][nf][1] * s1);
                float2 v1 = make_float2((float)acc[mi][nf][2] * s0,
                                        (float)acc[mi][nf][3] * s1);
                *(float2*)(out + r0 * OUT_D + col)       = v0;
                *(float2*)(out + (r0 + 8) * OUT_D + col) = v1;
            }
        }
    }
}

extern "C" void kernel_launch(void* const* d_in, const int* in_sizes, int n_in,
                              void* d_out, int out_size) {
    const float* x     = (const float*)d_in[0];
    const float* w     = (const float*)d_in[1];
    const float* scale = (const float*)d_in[2];
    float* out = (float*)d_out;

    prepack_w_kernel<<<256, 256>>>(w);

    cudaFuncSetAttribute(xnor_gemm_kernel,
                         cudaFuncAttributeMaxDynamicSharedMemorySize, SMEM_BYTES);
    xnor_gemm_kernel<<<N_ROWS / TILE_M, 512, SMEM_BYTES>>>(x, scale, out);
}

// round 4
// speedup vs baseline: 1.2558x; 1.2558x over previous
#include <cuda_runtime.h>
#include <cstdint>

#define N_ROWS   262144
#define IN_D     256
#define OUT_D    256

#define THREADS  256          // 8 warps
#define TILE_M   128          // rows per CTA
#define TILE_N   128          // out cols per CTA (nhalf)
#define KCHUNK   32           // K elements per pipeline chunk (= one mma k-step)
#define NCHUNK   (IN_D / KCHUNK)   // 8

#define LDA      (IN_D + 16)       // 272B pitch for s8 tiles
#define FP_PITCH 144               // bytes per row of fp32 chunk buf (32 floats + pad)
#define FBUF     (TILE_M * FP_PITCH)   // 18432

// smem layout (bytes)
#define SMEM_B     0
#define SMEM_A     (SMEM_B + TILE_N * LDA)          // 34816
#define SMEM_F     (SMEM_A + TILE_M * LDA)          // 69632
#define SMEM_SC    (SMEM_F + 2 * FBUF)              // 106496
#define SMEM_TOTAL (SMEM_SC + 512)                  // 107008

// ---------------- helpers ----------------
__device__ __forceinline__ uint32_t smem_u32(const void* p) {
    uint32_t a;
    asm("{ .reg .u64 t; cvta.to.shared.u64 t, %1; cvt.u32.u64 %0, t; }" : "=r"(a) : "l"(p));
    return a;
}
__device__ __forceinline__ void cp_async16(uint32_t dst, const void* src) {
    asm volatile("cp.async.cg.shared.global [%0], [%1], 16;" :: "r"(dst), "l"(src) : "memory");
}
#define CP_COMMIT()  asm volatile("cp.async.commit_group;" ::: "memory")
#define CP_WAIT(n)   asm volatile("cp.async.wait_group %0;" :: "n"(n) : "memory")

__device__ __forceinline__ int sgn(float f) { return (f > 0.0f) - (f < 0.0f); }

__device__ __forceinline__ uint32_t pack_sgn4(float4 v) {
    uint32_t b0 = (uint32_t)(uint8_t)(int8_t)sgn(v.x);
    uint32_t b1 = (uint32_t)(uint8_t)(int8_t)sgn(v.y);
    uint32_t b2 = (uint32_t)(uint8_t)(int8_t)sgn(v.z);
    uint32_t b3 = (uint32_t)(uint8_t)(int8_t)sgn(v.w);
    return b0 | (b1 << 8) | (b2 << 16) | (b3 << 24);
}

// prepacked sign(weight) s8 [OUT_D][IN_D]
__device__ __align__(16) int8_t g_wb[OUT_D * IN_D];

__global__ void prepack_w_kernel(const float* __restrict__ w) {
    int idx = blockIdx.x * 256 + threadIdx.x;
    g_wb[idx] = (int8_t)sgn(w[idx]);
}

// ---------------- main kernel ----------------
__global__ void __launch_bounds__(THREADS, 2)
xnor_gemm_kernel(const float* __restrict__ x,
                 const float* __restrict__ scale,
                 float* __restrict__ out) {
    extern __shared__ char smem[];
    const uint32_t sb = smem_u32(smem);
    int8_t* sB     = (int8_t*)(smem + SMEM_B);
    int8_t* sA     = (int8_t*)(smem + SMEM_A);
    float*  sScale = (float*)(smem + SMEM_SC);

    const int tid  = threadIdx.x;
    const int lane = tid & 31;
    const int warp = tid >> 5;
    const int tig  = lane & 3;
    const int grp  = lane >> 2;
    const int mw   = warp & 3;     // 4 M-warps (32 rows each)
    const int nw   = warp >> 2;    // 2 N-warps (64 cols each)

    const int mtile = blockIdx.x >> 1;
    const int nhalf = blockIdx.x & 1;
    const size_t mbase = (size_t)mtile * TILE_M;

    // ---- scale (plain load; visible after first barrier) ----
    if (tid < TILE_N) sScale[tid] = scale[nhalf * TILE_N + tid];

    // ---- group W: stage weight half [128][256] s8 via cp.async ----
    {
        const int8_t* wsrc = g_wb + (size_t)nhalf * TILE_N * IN_D;
        #pragma unroll
        for (int i = 0; i < 8; i++) {
            int fid = tid + i * THREADS;      // 0..2047 (16B units)
            int row = fid >> 4;               // 16 x 16B per 256B row
            int c16 = fid & 15;
            cp_async16(sb + SMEM_B + row * LDA + c16 * 16,
                       wsrc + row * IN_D + c16 * 16);
        }
        CP_COMMIT();
    }

    // ---- prologue: chunks 0 and 1 of x (raw fp32) ----
    const float* xrow = x + mbase * IN_D;
    #pragma unroll
    for (int c = 0; c < 2; c++) {
        #pragma unroll
        for (int i = 0; i < 4; i++) {
            int fid = tid + i * THREADS;      // 0..1023 (16B units)
            int row = fid >> 3;               // 8 x 16B per 32-float chunk row
            int c16 = fid & 7;
            cp_async16(sb + SMEM_F + c * FBUF + row * FP_PITCH + c16 * 16,
                       xrow + row * IN_D + c * KCHUNK + c16 * 4);
        }
        CP_COMMIT();
    }

    // ---- accumulators ----
    int acc[2][8][4];
    #pragma unroll
    for (int mi = 0; mi < 2; mi++)
        #pragma unroll
        for (int nf = 0; nf < 8; nf++)
            #pragma unroll
            for (int c = 0; c < 4; c++)
                acc[mi][nf][c] = 0;

    const int aRowBase = mw * 32;
    const int nColBase = nw * 64;

    // ---- pipelined mainloop over 8 k-chunks ----
    #pragma unroll
    for (int c = 0; c < NCHUNK; c++) {
        // wait for chunk c (own copies visible to self)
        if (c < NCHUNK - 1) { CP_WAIT(1); } else { CP_WAIT(0); }

        // convert chunk c: this thread reads exactly the bytes it copied
        const int buf = c & 1;
        {
            #pragma unroll
            for (int i = 0; i < 4; i++) {
                int fid = tid + i * THREADS;
                int row = fid >> 3;
                int c16 = fid & 7;
                float4 v = *(const float4*)(smem + SMEM_F + buf * FBUF + row * FP_PITCH + c16 * 16);
                *(uint32_t*)(sA + row * LDA + c * KCHUNK + c16 * 4) = pack_sgn4(v);
            }
        }

        // prefetch chunk c+2 into the buffer just drained
        if (c < NCHUNK - 2) {
            const int nc = c + 2;
            #pragma unroll
            for (int i = 0; i < 4; i++) {
                int fid = tid + i * THREADS;
                int row = fid >> 3;
                int c16 = fid & 7;
                cp_async16(sb + SMEM_F + buf * FBUF + row * FP_PITCH + c16 * 16,
                           xrow + row * IN_D + nc * KCHUNK + c16 * 4);
            }
            CP_COMMIT();
        }

        __syncthreads();   // strip c (and, at c=0, weights/scale) visible to all

        // ---- 16 mma per warp for this k-step ----
        const int kOff = c * KCHUNK;
        unsigned int a[2][4];
        #pragma unroll
        for (int mi = 0; mi < 2; mi++) {
            const int8_t* ap = sA + (aRowBase + mi * 16 + grp) * LDA + kOff + tig * 4;
            a[mi][0] = *(const unsigned int*)(ap);
            a[mi][1] = *(const unsigned int*)(ap + 8 * LDA);
            a[mi][2] = *(const unsigned int*)(ap + 16);
            a[mi][3] = *(const unsigned int*)(ap + 8 * LDA + 16);
        }
        #pragma unroll
        for (int nf = 0; nf < 8; nf++) {
            const int8_t* bp = sB + (nColBase + nf * 8 + grp) * LDA + kOff + tig * 4;
            unsigned int b0 = *(const unsigned int*)(bp);
            unsigned int b1 = *(const unsigned int*)(bp + 16);
            #pragma unroll
            for (int mi = 0; mi < 2; mi++) {
                asm volatile(
                    "mma.sync.aligned.m16n8k32.row.col.s32.s8.s8.s32 "
                    "{%0,%1,%2,%3}, {%4,%5,%6,%7}, {%8,%9}, {%0,%1,%2,%3};"
                    : "+r"(acc[mi][nf][0]), "+r"(acc[mi][nf][1]),
                      "+r"(acc[mi][nf][2]), "+r"(acc[mi][nf][3])
                    : "r"(a[mi][0]), "r"(a[mi][1]), "r"(a[mi][2]), "r"(a[mi][3]),
                      "r"(b0), "r"(b1));
            }
        }
    }

    // ---- epilogue: y = float(acc) * scale[col] ----
    const size_t outRow0 = mbase + mw * 32;
    const int colHalf = nhalf * TILE_N;
    #pragma unroll
    for (int mi = 0; mi < 2; mi++) {
        size_t r0 = outRow0 + mi * 16 + grp;
        #pragma unroll
        for (int nf = 0; nf < 8; nf++) {
            int col = nColBase + nf * 8 + tig * 2;
            float s0 = sScale[col];
            float s1 = sScale[col + 1];
            float2 v0 = make_float2((float)acc[mi][nf][0] * s0,
                                    (float)acc[mi][nf][1] * s1);
            float2 v1 = make_float2((float)acc[mi][nf][2] * s0,
                                    (float)acc[mi][nf][3] * s1);
            *(float2*)(out + r0 * OUT_D + colHalf + col)       = v0;
            *(float2*)(out + (r0 + 8) * OUT_D + colHalf + col) = v1;
        }
    }
}

extern "C" void kernel_launch(void* const* d_in, const int* in_sizes, int n_in,
                              void* d_out, int out_size) {
    const float* x     = (const float*)d_in[0];
    const float* w     = (const float*)d_in[1];
    const float* scale = (const float*)d_in[2];
    float* out = (float*)d_out;

    prepack_w_kernel<<<256, 256>>>(w);

    cudaFuncSetAttribute(xnor_gemm_kernel,
                         cudaFuncAttributeMaxDynamicSharedMemorySize, SMEM_TOTAL);
    xnor_gemm_kernel<<<(N_ROWS / TILE_M) * 2, THREADS, SMEM_TOTAL>>>(x, scale, out);
}

// round 9
// speedup vs baseline: 1.9542x; 1.5561x over previous
#include <cuda_runtime.h>
#include <cstdint>

#define N_ROWS   262144
#define IN_D     256
#define OUT_D    256

#define THREADS  256          // 8 warps
#define TILE_M   128          // rows per CTA
#define TILE_N   128          // out cols per CTA (nhalf)
#define KCHUNK   32           // K elements per pipeline chunk (= one mma k-step)
#define NCHUNK   (IN_D / KCHUNK)   // 8

#define LDA      (IN_D + 16)       // 272B pitch for fp8 tiles
#define FP_PITCH 144               // bytes per row of fp32 chunk buf (32 floats + pad)
#define FBUF     (TILE_M * FP_PITCH)   // 18432

// smem layout (bytes)
#define SMEM_B     0
#define SMEM_A     (SMEM_B + TILE_N * LDA)          // 34816
#define SMEM_F     (SMEM_A + TILE_M * LDA)          // 69632
#define SMEM_SC    (SMEM_F + 2 * FBUF)              // 106496
#define SMEM_TOTAL (SMEM_SC + 512)                  // 107008

// e4m3 encodings: +1.0 = 0x38, -1.0 = 0xB8, 0.0 = 0x00
#define E4M3_P1  0x38u
#define E4M3_M1  0xB8u

// ---------------- helpers ----------------
__device__ __forceinline__ uint32_t smem_u32(const void* p) {
    uint32_t a;
    asm("{ .reg .u64 t; cvta.to.shared.u64 t, %1; cvt.u32.u64 %0, t; }" : "=r"(a) : "l"(p));
    return a;
}
__device__ __forceinline__ void cp_async16(uint32_t dst, const void* src) {
    asm volatile("cp.async.cg.shared.global [%0], [%1], 16;" :: "r"(dst), "l"(src) : "memory");
}
#define CP_COMMIT()  asm volatile("cp.async.commit_group;" ::: "memory")
#define CP_WAIT(n)   asm volatile("cp.async.wait_group %0;" :: "n"(n) : "memory")

// sign(f) as e4m3 byte (sign(0)=0 matches jnp.sign)
__device__ __forceinline__ uint32_t sgn_e4m3(float f) {
    return (f > 0.0f) ? E4M3_P1 : ((f < 0.0f) ? E4M3_M1 : 0u);
}

__device__ __forceinline__ uint32_t pack_sgn4(float4 v) {
    return sgn_e4m3(v.x) | (sgn_e4m3(v.y) << 8) | (sgn_e4m3(v.z) << 16) | (sgn_e4m3(v.w) << 24);
}

// prepacked sign(weight) as e4m3 [OUT_D][IN_D]
__device__ __align__(16) uint8_t g_wb[OUT_D * IN_D];

__global__ void prepack_w_kernel(const float* __restrict__ w) {
    int idx = blockIdx.x * 256 + threadIdx.x;
    g_wb[idx] = (uint8_t)sgn_e4m3(w[idx]);
}

// ---------------- main kernel ----------------
__global__ void __launch_bounds__(THREADS, 2)
xnor_gemm_kernel(const float* __restrict__ x,
                 const float* __restrict__ scale,
                 float* __restrict__ out) {
    extern __shared__ char smem[];
    const uint32_t sb = smem_u32(smem);
    uint8_t* sB    = (uint8_t*)(smem + SMEM_B);
    uint8_t* sA    = (uint8_t*)(smem + SMEM_A);
    float*  sScale = (float*)(smem + SMEM_SC);

    const int tid  = threadIdx.x;
    const int lane = tid & 31;
    const int warp = tid >> 5;
    const int tig  = lane & 3;
    const int grp  = lane >> 2;
    const int mw   = warp & 3;     // 4 M-warps (32 rows each)
    const int nw   = warp >> 2;    // 2 N-warps (64 cols each)

    const int mtile = blockIdx.x >> 1;
    const int nhalf = blockIdx.x & 1;
    const size_t mbase = (size_t)mtile * TILE_M;

    // ---- scale (plain load; visible after first barrier) ----
    if (tid < TILE_N) sScale[tid] = scale[nhalf * TILE_N + tid];

    // ---- stage weight half [128][256] e4m3 via cp.async ----
    {
        const uint8_t* wsrc = g_wb + (size_t)nhalf * TILE_N * IN_D;
        #pragma unroll
        for (int i = 0; i < 8; i++) {
            int fid = tid + i * THREADS;      // 0..2047 (16B units)
            int row = fid >> 4;               // 16 x 16B per 256B row
            int c16 = fid & 15;
            cp_async16(sb + SMEM_B + row * LDA + c16 * 16,
                       wsrc + row * IN_D + c16 * 16);
        }
        CP_COMMIT();
    }

    // ---- prologue: chunks 0 and 1 of x (raw fp32) ----
    const float* xrow = x + mbase * IN_D;
    #pragma unroll
    for (int c = 0; c < 2; c++) {
        #pragma unroll
        for (int i = 0; i < 4; i++) {
            int fid = tid + i * THREADS;      // 0..1023 (16B units)
            int row = fid >> 3;               // 8 x 16B per 32-float chunk row
            int c16 = fid & 7;
            cp_async16(sb + SMEM_F + c * FBUF + row * FP_PITCH + c16 * 16,
                       xrow + row * IN_D + c * KCHUNK + c16 * 4);
        }
        CP_COMMIT();
    }

    // ---- accumulators (f32) ----
    float acc[2][8][4];
    #pragma unroll
    for (int mi = 0; mi < 2; mi++)
        #pragma unroll
        for (int nf = 0; nf < 8; nf++)
            #pragma unroll
            for (int c = 0; c < 4; c++)
                acc[mi][nf][c] = 0.0f;

    const int aRowBase = mw * 32;
    const int nColBase = nw * 64;

    // ---- pipelined mainloop over 8 k-chunks ----
    #pragma unroll
    for (int c = 0; c < NCHUNK; c++) {
        // wait for chunk c (own copies visible to self)
        if (c < NCHUNK - 1) { CP_WAIT(1); } else { CP_WAIT(0); }

        // convert chunk c: this thread reads exactly the bytes it copied
        const int buf = c & 1;
        {
            #pragma unroll
            for (int i = 0; i < 4; i++) {
                int fid = tid + i * THREADS;
                int row = fid >> 3;
                int c16 = fid & 7;
                float4 v = *(const float4*)(smem + SMEM_F + buf * FBUF + row * FP_PITCH + c16 * 16);
                *(uint32_t*)(sA + row * LDA + c * KCHUNK + c16 * 4) = pack_sgn4(v);
            }
        }

        // prefetch chunk c+2 into the buffer just drained
        if (c < NCHUNK - 2) {
            const int nc = c + 2;
            #pragma unroll
            for (int i = 0; i < 4; i++) {
                int fid = tid + i * THREADS;
                int row = fid >> 3;
                int c16 = fid & 7;
                cp_async16(sb + SMEM_F + buf * FBUF + row * FP_PITCH + c16 * 16,
                           xrow + row * IN_D + nc * KCHUNK + c16 * 4);
            }
            CP_COMMIT();
        }

        __syncthreads();   // strip c (and, at c=0, weights/scale) visible to all

        // ---- 16 fp8 QMMA per warp for this k-step ----
        const int kOff = c * KCHUNK;
        unsigned int a[2][4];
        #pragma unroll
        for (int mi = 0; mi < 2; mi++) {
            const uint8_t* ap = sA + (aRowBase + mi * 16 + grp) * LDA + kOff + tig * 4;
            a[mi][0] = *(const unsigned int*)(ap);
            a[mi][1] = *(const unsigned int*)(ap + 8 * LDA);
            a[mi][2] = *(const unsigned int*)(ap + 16);
            a[mi][3] = *(const unsigned int*)(ap + 8 * LDA + 16);
        }
        #pragma unroll
        for (int nf = 0; nf < 8; nf++) {
            const uint8_t* bp = sB + (nColBase + nf * 8 + grp) * LDA + kOff + tig * 4;
            unsigned int b0 = *(const unsigned int*)(bp);
            unsigned int b1 = *(const unsigned int*)(bp + 16);
            #pragma unroll
            for (int mi = 0; mi < 2; mi++) {
                asm volatile(
                    "mma.sync.aligned.m16n8k32.row.col.f32.e4m3.e4m3.f32 "
                    "{%0,%1,%2,%3}, {%4,%5,%6,%7}, {%8,%9}, {%0,%1,%2,%3};"
                    : "+f"(acc[mi][nf][0]), "+f"(acc[mi][nf][1]),
                      "+f"(acc[mi][nf][2]), "+f"(acc[mi][nf][3])
                    : "r"(a[mi][0]), "r"(a[mi][1]), "r"(a[mi][2]), "r"(a[mi][3]),
                      "r"(b0), "r"(b1));
            }
        }
    }

    // ---- epilogue: y = acc * scale[col] (acc already f32) ----
    const size_t outRow0 = mbase + mw * 32;
    const int colHalf = nhalf * TILE_N;
    #pragma unroll
    for (int mi = 0; mi < 2; mi++) {
        size_t r0 = outRow0 + mi * 16 + grp;
        #pragma unroll
        for (int nf = 0; nf < 8; nf++) {
            int col = nColBase + nf * 8 + tig * 2;
            float s0 = sScale[col];
            float s1 = sScale[col + 1];
            float2 v0 = make_float2(acc[mi][nf][0] * s0, acc[mi][nf][1] * s1);
            float2 v1 = make_float2(acc[mi][nf][2] * s0, acc[mi][nf][3] * s1);
            *(float2*)(out + r0 * OUT_D + colHalf + col)       = v0;
            *(float2*)(out + (r0 + 8) * OUT_D + colHalf + col) = v1;
        }
    }
}

extern "C" void kernel_launch(void* const* d_in, const int* in_sizes, int n_in,
                              void* d_out, int out_size) {
    const float* x     = (const float*)d_in[0];
    const float* w     = (const float*)d_in[1];
    const float* scale = (const float*)d_in[2];
    float* out = (float*)d_out;

    prepack_w_kernel<<<256, 256>>>(w);

    cudaFuncSetAttribute(xnor_gemm_kernel,
                         cudaFuncAttributeMaxDynamicSharedMemorySize, SMEM_TOTAL);
    xnor_gemm_kernel<<<(N_ROWS / TILE_M) * 2, THREADS, SMEM_TOTAL>>>(x, scale, out);
}